// round 17
// baseline (speedup 1.0000x reference)
#include <cuda_runtime.h>
#include <cuda_fp16.h>
#include <cstdint>
#include <cstddef>

// Problem constants
#define BB   2
#define NN   2048
#define DIMM 2048
#define HH   16
#define DD   128
#define DI   2048          // HEADS * DIM_HEAD
#define TDI  6144          // 3 * DI
#define QK_SCALE 0.08838834764831845f  // 128^-0.5

#define NX  ((size_t)BB * NN * DIMM)   // x elems
#define NW1 ((size_t)DIMM * TDI)       // w_qkv elems
#define NW2 ((size_t)DI * DIMM)        // w_out elems

// fp16 scratch
__device__ __half g_xh  [NX];
__device__ __half g_wqh [NW1];
__device__ __half g_woh [NW2];
__device__ __half g_qkvh[(size_t)BB * NN * TDI];
__device__ __half g_atth[(size_t)BB * NN * DI];

// ---------------------------------------------------------------------------
// helpers
// ---------------------------------------------------------------------------
__device__ __forceinline__ uint32_t pack_h2(float lo, float hi) {
    __half2 h = __floats2half2_rn(lo, hi);
    return *reinterpret_cast<uint32_t*>(&h);
}

__device__ __forceinline__ void mma_fp16(float c[4],
                                         const uint32_t a[4],
                                         const uint32_t b0, const uint32_t b1) {
    asm volatile(
        "mma.sync.aligned.m16n8k16.row.col.f32.f16.f16.f32 "
        "{%0,%1,%2,%3}, {%4,%5,%6,%7}, {%8,%9}, {%0,%1,%2,%3};"
        : "+f"(c[0]), "+f"(c[1]), "+f"(c[2]), "+f"(c[3])
        : "r"(a[0]), "r"(a[1]), "r"(a[2]), "r"(a[3]),
          "r"(b0), "r"(b1));
}

__device__ __forceinline__ void ldsm4(uint32_t r[4], uint32_t saddr) {
    asm volatile("ldmatrix.sync.aligned.m8n8.x4.shared.b16 {%0,%1,%2,%3}, [%4];"
        : "=r"(r[0]), "=r"(r[1]), "=r"(r[2]), "=r"(r[3]) : "r"(saddr));
}

__device__ __forceinline__ void ldsm4t(uint32_t r[4], uint32_t saddr) {
    asm volatile("ldmatrix.sync.aligned.m8n8.x4.trans.shared.b16 {%0,%1,%2,%3}, [%4];"
        : "=r"(r[0]), "=r"(r[1]), "=r"(r[2]), "=r"(r[3]) : "r"(saddr));
}

__device__ __forceinline__ void cp16(uint32_t smem_dst, const void* gptr) {
    asm volatile("cp.async.cg.shared.global [%0], [%1], 16;"
                 :: "r"(smem_dst), "l"(gptr) : "memory");
}
#define CP_COMMIT() asm volatile("cp.async.commit_group;" ::: "memory")
#define CP_WAIT0()  asm volatile("cp.async.wait_group 0;" ::: "memory")

// FMA-pipe exp for y <= 0 (rel err ~4e-5). Runs parallel to MUFU __expf.
__device__ __forceinline__ float fexp_poly(float y) {
    float t = fmaxf(y, -30.0f) * 1.4426950408889634f;
    float z = t + 12582912.0f;
    int   i = __float_as_int(z);
    float f = t - (z - 12582912.0f);
    float p = 0.0096180f;
    p = fmaf(p, f, 0.0555041f);
    p = fmaf(p, f, 0.2402265f);
    p = fmaf(p, f, 0.6931472f);
    p = fmaf(p, f, 1.0f);
    float s = __int_as_float((i - 1262485377) << 23);
    return p * s;
}

// ---------------------------------------------------------------------------
// Pre-convert: fp32 inputs -> fp16 scratch (one streaming pass)
// ---------------------------------------------------------------------------
__global__ __launch_bounds__(256) void convert_fp16(const float* __restrict__ x,
                                                    const float* __restrict__ w1,
                                                    const float* __restrict__ w2)
{
    const size_t idx = (size_t)blockIdx.x * blockDim.x + threadIdx.x;
    const size_t stride = (size_t)gridDim.x * blockDim.x;

    for (size_t i = idx; i < NX / 4; i += stride) {
        float4 v = ((const float4*)x)[i];
        ((uint2*)g_xh)[i] = make_uint2(pack_h2(v.x, v.y), pack_h2(v.z, v.w));
    }
    for (size_t i = idx; i < NW1 / 4; i += stride) {
        float4 v = ((const float4*)w1)[i];
        ((uint2*)g_wqh)[i] = make_uint2(pack_h2(v.x, v.y), pack_h2(v.z, v.w));
    }
    for (size_t i = idx; i < NW2 / 4; i += stride) {
        float4 v = ((const float4*)w2)[i];
        ((uint2*)g_woh)[i] = make_uint2(pack_h2(v.x, v.y), pack_h2(v.z, v.w));
    }
}

// ---------------------------------------------------------------------------
// fp16 GEMM, cp.async staging, 64x64 warp tiles, BK=64.
// C[M,Nc] = A[M,K] @ B[K,Nc]; fp16 operands in gmem. Block 128x128, BK=64,
// 128 threads = 4 warps (2m x 2n). Per chunk: 8+8 cp.async segs/thread,
// 4 k16 steps x (8 LDSM + 32 MMA) per warp, ONE barrier.
// mode 0: A=g_xh,  B=g_wqh, C=g_qkvh (fp16; QK_SCALE folded for col0<DI)
// mode 1: A=g_atth,B=g_woh, C=Cp (fp32 out)
// ---------------------------------------------------------------------------
#define SA 72                        // halves per A row (64 + 8 pad)
#define SB 136                       // halves per B row (128 + 8 pad)
#define ABUF_B (128 * SA * 2)        // 18432
#define BBUF_B (64 * SB * 2)         // 17408
#define GEMM_SMEM_BYTES (2 * ABUF_B + 2 * BBUF_B)   // 71680

__global__ __launch_bounds__(128, 2) void gemm_fp16(float* __restrict__ Cp,
                                                    int M, int Nc, int K, int mode)
{
    const __half* A  = (mode == 0) ? g_xh  : g_atth;
    const __half* Bh = (mode == 0) ? g_wqh : g_woh;

    extern __shared__ char dsm[];
    const uint32_t sbase = (uint32_t)__cvta_generic_to_shared(dsm);

    const int tid  = threadIdx.x;
    const int row0 = blockIdx.y * 128;
    const int col0 = blockIdx.x * 128;
    const int wid  = tid >> 5;
    const int lane = tid & 31;
    const int g    = lane >> 2;
    const int tg   = lane & 3;
    const int wm   = (wid & 1) * 64;     // warp row offset
    const int wn   = (wid >> 1) * 64;    // warp col offset
    const int qd   = lane >> 3;
    const int rr   = lane & 7;

    const uint32_t a_off0 = (uint32_t)(((wm + (qd & 1) * 8 + rr) * SA + (qd >> 1) * 8) * 2);
    const uint32_t b_off0 = (uint32_t)((((qd & 1) * 8 + rr) * SB + wn + (qd >> 1) * 8) * 2);

    float acc[4][8][4];
#pragma unroll
    for (int mi = 0; mi < 4; mi++)
#pragma unroll
        for (int ni = 0; ni < 8; ni++)
#pragma unroll
            for (int r = 0; r < 4; r++) acc[mi][ni][r] = 0.f;

    // cp.async seg mapping (128 threads, 8 segs each for A and B):
    // A: 1024 segs of 16B (8 halves): seg -> row=seg>>3, col8=(seg&7)*8
    // B: 1024 segs: seg -> row=seg>>4, col8=(seg&15)*8
    uint32_t dA[8], dB[8];
    const __half* sAg[8];
    const __half* sBg[8];
#pragma unroll
    for (int j = 0; j < 8; j++) {
        int sa = tid + 128 * j;
        int ar = sa >> 3, ac = (sa & 7) * 8;
        dA[j]  = sbase + (ar * SA + ac) * 2;
        sAg[j] = A + (size_t)(row0 + ar) * K + ac;
        int sb = tid + 128 * j;
        int br = sb >> 4, bc = (sb & 15) * 8;
        dB[j]  = sbase + 2 * ABUF_B + (br * SB + bc) * 2;
        sBg[j] = Bh + (size_t)br * Nc + col0 + bc;
    }

    auto issue_loads = [&](int kt, int buf) {
#pragma unroll
        for (int j = 0; j < 8; j++) {
            cp16(dA[j] + buf * ABUF_B, sAg[j] + kt);
            cp16(dB[j] + buf * BBUF_B, sBg[j] + (size_t)kt * Nc);
        }
        CP_COMMIT();
    };

    auto compute = [&](int buf) {
        const uint32_t ab = sbase + buf * ABUF_B + a_off0;
        const uint32_t bb = sbase + 2 * ABUF_B + buf * BBUF_B + b_off0;
#pragma unroll
        for (int ks = 0; ks < 4; ks++) {
            uint32_t bf[8][2];
#pragma unroll
            for (int pr = 0; pr < 4; pr++) {
                uint32_t t[4];
                ldsm4t(t, bb + ks * (16 * SB * 2) + pr * 32);
                bf[2 * pr    ][0] = t[0]; bf[2 * pr    ][1] = t[1];
                bf[2 * pr + 1][0] = t[2]; bf[2 * pr + 1][1] = t[3];
            }
#pragma unroll
            for (int mi = 0; mi < 4; mi++) {
                uint32_t af[4];
                ldsm4(af, ab + mi * (16 * SA * 2) + ks * 32);
#pragma unroll
                for (int ni = 0; ni < 8; ni++)
                    mma_fp16(acc[mi][ni], af, bf[ni][0], bf[ni][1]);
            }
        }
    };

    issue_loads(0, 0);

    int buf = 0;
    for (int kt = 0; kt < K; kt += 64) {
        CP_WAIT0();
        __syncthreads();
        if (kt + 64 < K) issue_loads(kt + 64, buf ^ 1);
        compute(buf);
        buf ^= 1;
    }

    // Epilogue
    if (mode == 0) {
        const float sc = (col0 < DI) ? QK_SCALE : 1.0f;   // fold Q scaling
        __half* C = g_qkvh;
#pragma unroll
        for (int mi = 0; mi < 4; mi++) {
#pragma unroll
            for (int ni = 0; ni < 8; ni++) {
                const int row = row0 + wm + mi * 16;
                const int col = col0 + wn + ni * 8 + 2 * tg;
                *(uint32_t*)&C[(size_t)(row + g    ) * Nc + col] =
                    pack_h2(acc[mi][ni][0] * sc, acc[mi][ni][1] * sc);
                *(uint32_t*)&C[(size_t)(row + g + 8) * Nc + col] =
                    pack_h2(acc[mi][ni][2] * sc, acc[mi][ni][3] * sc);
            }
        }
    } else {
#pragma unroll
        for (int mi = 0; mi < 4; mi++) {
#pragma unroll
            for (int ni = 0; ni < 8; ni++) {
                const int row = row0 + wm + mi * 16;
                const int col = col0 + wn + ni * 8 + 2 * tg;
                *(float2*)&Cp[(size_t)(row + g    ) * Nc + col] =
                    make_float2(acc[mi][ni][0], acc[mi][ni][1]);
                *(float2*)&Cp[(size_t)(row + g + 8) * Nc + col] =
                    make_float2(acc[mi][ni][2], acc[mi][ni][3]);
            }
        }
    }
}

// ---------------------------------------------------------------------------
// Flash attention (causal): fp16 in/out, fp16 mma, hybrid MUFU/poly exp.
// (unchanged from Round 15/16 — ~230 us)
// ---------------------------------------------------------------------------
#define SQ  136
#define SP  72
#define QH_B 0
#define KH_B (64 * SQ * 2)
#define VH_B (2 * 64 * SQ * 2)
#define PH_B (3 * 64 * SQ * 2)
#define ATT_SMEM_BYTES (3 * 64 * SQ * 2 + 64 * SP * 2)   // 61440

__global__ __launch_bounds__(128, 3) void attn_mma()
{
    extern __shared__ char dsm[];
    const uint32_t sbase = (uint32_t)__cvta_generic_to_shared(dsm);

    const int bh  = blockIdx.y;
    const int b   = bh >> 4;
    const int h   = bh & 15;
    const int m0  = blockIdx.x * 64;
    const int tid = threadIdx.x;
    const int wid = tid >> 5;
    const int lane = tid & 31;
    const int g   = lane >> 2;
    const int tg  = lane & 3;
    const int qd  = lane >> 3;
    const int rr  = lane & 7;

    const int r0  = wid * 16 + g;
    const int r1  = r0 + 8;
    const int gr0 = m0 + r0;
    const int gr1 = m0 + r1;

    const uint32_t qa_base = sbase + QH_B +
        ((wid * 16 + (qd & 1) * 8 + rr) * SQ + (qd >> 1) * 8) * 2;
    const uint32_t kb_base = sbase + KH_B +
        (((qd >> 1) * 8 + rr) * SQ + (qd & 1) * 8) * 2;
    const uint32_t vb_base = sbase + VH_B +
        (((qd & 1) * 8 + rr) * SQ + (qd >> 1) * 8) * 2;
    const uint32_t pa_base = sbase + PH_B +
        ((wid * 16 + (qd & 1) * 8 + rr) * SP + (qd >> 1) * 8) * 2;

    // ---- Load Q [64 x 128] fp16 verbatim (already scaled) ----
    const __half* Qg = g_qkvh + ((size_t)(b * NN + m0)) * TDI + h * DD;
#pragma unroll
    for (int l = 0; l < 8; l++) {
        int fl = tid + l * 128;
        int r  = fl >> 4;
        int d8 = (fl & 15) * 8;
        *(uint4*)(dsm + QH_B + (r * SQ + d8) * 2) =
            *(const uint4*)(Qg + (size_t)r * TDI + d8);
    }

    float m_r[2] = {-1e30f, -1e30f};
    float l_r[2] = {0.f, 0.f};
    float O[16][4];
#pragma unroll
    for (int ni = 0; ni < 16; ni++)
#pragma unroll
        for (int r = 0; r < 4; r++) O[ni][r] = 0.f;

    const int ntiles = blockIdx.x + 1;
    for (int t = 0; t < ntiles; t++) {
        const int k0 = t * 64;
        __syncthreads();

        const __half* Kg = g_qkvh + ((size_t)(b * NN + k0)) * TDI + DI + h * DD;
        const __half* Vg = Kg + DI;
#pragma unroll
        for (int l = 0; l < 8; l++) {
            int fl = tid + l * 128;
            int r  = fl >> 4;
            int d8 = (fl & 15) * 8;
            *(uint4*)(dsm + KH_B + (r * SQ + d8) * 2) =
                *(const uint4*)(Kg + (size_t)r * TDI + d8);
            *(uint4*)(dsm + VH_B + (r * SQ + d8) * 2) =
                *(const uint4*)(Vg + (size_t)r * TDI + d8);
        }
        __syncthreads();

        // ---- S = Q @ K^T ----
        float S[8][4];
#pragma unroll
        for (int ni = 0; ni < 8; ni++)
#pragma unroll
            for (int r = 0; r < 4; r++) S[ni][r] = 0.f;

#pragma unroll
        for (int ks = 0; ks < 8; ks++) {
            uint32_t af[4];
            ldsm4(af, qa_base + ks * 32);
#pragma unroll
            for (int pr = 0; pr < 4; pr++) {
                uint32_t bt[4];
                ldsm4(bt, kb_base + pr * (16 * SQ * 2) + ks * 32);
                mma_fp16(S[2 * pr    ], af, bt[0], bt[1]);
                mma_fp16(S[2 * pr + 1], af, bt[2], bt[3]);
            }
        }

        if (t == ntiles - 1) {
#pragma unroll
            for (int ni = 0; ni < 8; ni++) {
                const int c = k0 + ni * 8 + 2 * tg;
                if (c     > gr0) S[ni][0] = -1e30f;
                if (c + 1 > gr0) S[ni][1] = -1e30f;
                if (c     > gr1) S[ni][2] = -1e30f;
                if (c + 1 > gr1) S[ni][3] = -1e30f;
            }
        }

        // ---- Softmax (hybrid exp) ----
        float mx0 = -1e30f, mx1 = -1e30f;
#pragma unroll
        for (int ni = 0; ni < 8; ni++) {
            mx0 = fmaxf(mx0, fmaxf(S[ni][0], S[ni][1]));
            mx1 = fmaxf(mx1, fmaxf(S[ni][2], S[ni][3]));
        }
        mx0 = fmaxf(mx0, __shfl_xor_sync(0xffffffffu, mx0, 1));
        mx0 = fmaxf(mx0, __shfl_xor_sync(0xffffffffu, mx0, 2));
        mx1 = fmaxf(mx1, __shfl_xor_sync(0xffffffffu, mx1, 1));
        mx1 = fmaxf(mx1, __shfl_xor_sync(0xffffffffu, mx1, 2));

        const float mn0 = fmaxf(m_r[0], mx0);
        const float mn1 = fmaxf(m_r[1], mx1);
        const float sc0 = __expf(m_r[0] - mn0);
        const float sc1 = __expf(m_r[1] - mn1);

        float sum0 = 0.f, sum1 = 0.f;
        char* p0 = dsm + PH_B + (r0 * SP + 2 * tg) * 2;
        char* p1 = dsm + PH_B + (r1 * SP + 2 * tg) * 2;
#pragma unroll
        for (int ni = 0; ni < 8; ni++) {
            float p00, p01, p10, p11;
            if (ni & 1) {
                p00 = fexp_poly(S[ni][0] - mn0);
                p01 = fexp_poly(S[ni][1] - mn0);
                p10 = fexp_poly(S[ni][2] - mn1);
                p11 = fexp_poly(S[ni][3] - mn1);
            } else {
                p00 = __expf(S[ni][0] - mn0);
                p01 = __expf(S[ni][1] - mn0);
                p10 = __expf(S[ni][2] - mn1);
                p11 = __expf(S[ni][3] - mn1);
            }
            sum0 += p00 + p01;
            sum1 += p10 + p11;
            *(uint32_t*)(p0 + ni * 16) = pack_h2(p00, p01);
            *(uint32_t*)(p1 + ni * 16) = pack_h2(p10, p11);
        }
        sum0 += __shfl_xor_sync(0xffffffffu, sum0, 1);
        sum0 += __shfl_xor_sync(0xffffffffu, sum0, 2);
        sum1 += __shfl_xor_sync(0xffffffffu, sum1, 1);
        sum1 += __shfl_xor_sync(0xffffffffu, sum1, 2);

        l_r[0] = l_r[0] * sc0 + sum0;  m_r[0] = mn0;
        l_r[1] = l_r[1] * sc1 + sum1;  m_r[1] = mn1;

#pragma unroll
        for (int ni = 0; ni < 16; ni++) {
            O[ni][0] *= sc0; O[ni][1] *= sc0;
            O[ni][2] *= sc1; O[ni][3] *= sc1;
        }
        __syncwarp();

        // ---- O += P @ V ----
#pragma unroll
        for (int ks = 0; ks < 4; ks++) {
            uint32_t af[4];
            ldsm4(af, pa_base + ks * 32);
#pragma unroll
            for (int pr = 0; pr < 8; pr++) {
                uint32_t bt[4];
                ldsm4t(bt, vb_base + pr * 32 + ks * (16 * SQ * 2));
                mma_fp16(O[2 * pr    ], af, bt[0], bt[1]);
                mma_fp16(O[2 * pr + 1], af, bt[2], bt[3]);
            }
        }
    }

    // ---- Epilogue: normalize, write fp16 ----
    const float inv0 = 1.0f / l_r[0];
    const float inv1 = 1.0f / l_r[1];
    __half* O0 = g_atth + ((size_t)(b * NN + gr0)) * DI + h * DD;
    __half* O1 = g_atth + ((size_t)(b * NN + gr1)) * DI + h * DD;
#pragma unroll
    for (int ni = 0; ni < 16; ni++) {
        const int c = ni * 8 + 2 * tg;
        *(uint32_t*)&O0[c] = pack_h2(O[ni][0] * inv0, O[ni][1] * inv0);
        *(uint32_t*)&O1[c] = pack_h2(O[ni][2] * inv1, O[ni][3] * inv1);
    }
}

// ---------------------------------------------------------------------------
// Launch
// ---------------------------------------------------------------------------
extern "C" void kernel_launch(void* const* d_in, const int* in_sizes, int n_in,
                              void* d_out, int out_size)
{
    const float* x     = (const float*)d_in[0];   // [2, 2048, 2048]
    const float* w_qkv = (const float*)d_in[1];   // [2048, 6144]
    const float* w_out = (const float*)d_in[2];   // [2048, 2048]
    float* out = (float*)d_out;                   // [2, 2048, 2048]

    cudaFuncSetAttribute(gemm_fp16,
                         cudaFuncAttributeMaxDynamicSharedMemorySize,
                         GEMM_SMEM_BYTES);
    cudaFuncSetAttribute(attn_mma,
                         cudaFuncAttributeMaxDynamicSharedMemorySize,
                         ATT_SMEM_BYTES);

    // 0) fp32 -> fp16 conversion of inputs
    convert_fp16<<<592, 256>>>(x, w_qkv, w_out);

    // 1) QKV projection -> g_qkvh (fp16, Q pre-scaled)
    gemm_fp16<<<dim3(TDI / 128, (BB * NN) / 128), 128, GEMM_SMEM_BYTES>>>(
        nullptr, BB * NN, TDI, DIMM, 0);

    // 2) Causal flash attention: g_qkvh -> g_atth
    attn_mma<<<dim3(NN / 64, BB * HH), 128, ATT_SMEM_BYTES>>>();

    // 3) Output projection: g_atth @ g_woh -> out (fp32)
    gemm_fp16<<<dim3(DIMM / 128, (BB * NN) / 128), 128, GEMM_SMEM_BYTES>>>(
        out, BB * NN, DIMM, DIMM, 1);
}